// round 15
// baseline (speedup 1.0000x reference)
#include <cuda_runtime.h>
#include <cuda_fp16.h>
#include <cstdint>

// Problem constants
#define BATCH 2
#define SEQ   2048
#define EMB   1024
#define NH    16
#define HD    64
#define MROWS (BATCH * SEQ)      // 4096
#define BH    (BATCH * NH)       // 32
#define NW    (EMB * EMB)        // 1048576

// Scratch (device globals)
__device__ __half g_xh[MROWS * EMB];    // activation hi (x, later attn-out)
__device__ __half g_Wh4[4 * NW];        // weight hi x4 (Wq,Wk,Wv,Wo)
__device__ __half g_Qh[BH * SEQ * HD];  // [b,h,s,d] fp16 (pre-scaled by 0.125*log2e)
__device__ __half g_Kh[BH * SEQ * HD];
__device__ __half g_Vh[BH * SEQ * HD];

// ---------------------------------------------------------------------------
// helpers
// ---------------------------------------------------------------------------
__device__ __forceinline__ uint32_t smem_u32(const void* p) {
    uint32_t a;
    asm("{ .reg .u64 t; cvta.to.shared.u64 t, %1; cvt.u32.u64 %0, t; }"
        : "=r"(a) : "l"(p));
    return a;
}
__device__ __forceinline__ void ldsm_x4(uint32_t* r, uint32_t addr) {
    asm volatile("ldmatrix.sync.aligned.m8n8.x4.shared.b16 {%0,%1,%2,%3}, [%4];"
                 : "=r"(r[0]), "=r"(r[1]), "=r"(r[2]), "=r"(r[3]) : "r"(addr));
}
__device__ __forceinline__ void ldsm_x4_t(uint32_t* r, uint32_t addr) {
    asm volatile("ldmatrix.sync.aligned.m8n8.x4.trans.shared.b16 {%0,%1,%2,%3}, [%4];"
                 : "=r"(r[0]), "=r"(r[1]), "=r"(r[2]), "=r"(r[3]) : "r"(addr));
}
__device__ __forceinline__ void mma16816(float* c, const uint32_t* a, const uint32_t* b) {
    asm volatile("mma.sync.aligned.m16n8k16.row.col.f32.f16.f16.f32 "
                 "{%0,%1,%2,%3}, {%4,%5,%6,%7}, {%8,%9}, {%0,%1,%2,%3};"
                 : "+f"(c[0]), "+f"(c[1]), "+f"(c[2]), "+f"(c[3])
                 : "r"(a[0]), "r"(a[1]), "r"(a[2]), "r"(a[3]),
                   "r"(b[0]), "r"(b[1]));
}
__device__ __forceinline__ uint32_t pack_h2(__half a, __half b) {
    __half2 h = __halves2half2(a, b);
    return *reinterpret_cast<uint32_t*>(&h);
}
__device__ __forceinline__ uint32_t ex2_h2(float lo, float hi) {
    uint32_t h, r;
    asm("cvt.rn.f16x2.f32 %0, %1, %2;" : "=r"(h) : "f"(hi), "f"(lo));
    asm("ex2.approx.f16x2 %0, %1;" : "=r"(r) : "r"(h));
    return r;
}
__device__ __forceinline__ uint32_t hadd2(uint32_t a, uint32_t b) {
    uint32_t r;
    asm("add.f16x2 %0, %1, %2;" : "=r"(r) : "r"(a), "r"(b));
    return r;
}
__device__ __forceinline__ void cp16(uint32_t saddr, const void* g) {
    asm volatile("cp.async.cg.shared.global [%0], [%1], 16;"
                 :: "r"(saddr), "l"(g) : "memory");
}
#define CP_COMMIT() asm volatile("cp.async.commit_group;" ::: "memory")
#define CP_WAIT0()  asm volatile("cp.async.wait_group 0;" ::: "memory")

#define QSCALE 0.18033688f   // 0.125 * log2(e)
#define SOFF   8.0f          // fixed softmax offset (log2 units); cancels in p/l

// ---------------------------------------------------------------------------
// merged fp32->fp16 convert, 4 float4 per thread (MLP=4):
// y=0..3 -> W slots, y=4..7 -> quarters of x
// ---------------------------------------------------------------------------
__device__ __forceinline__ void cvt4(const float* __restrict__ src,
                                     __half* __restrict__ hi, int i) {
    float4 v = ((const float4*)src)[i];
    ((uint2*)hi)[i] = make_uint2(
        pack_h2(__float2half_rn(v.x), __float2half_rn(v.y)),
        pack_h2(__float2half_rn(v.z), __float2half_rn(v.w)));
}

__global__ void __launch_bounds__(256)
cvt_all(const float* __restrict__ x,
        const float* __restrict__ w0, const float* __restrict__ w1,
        const float* __restrict__ w2, const float* __restrict__ w3,
        __half* __restrict__ wh4, __half* __restrict__ xh)
{
    const int y  = blockIdx.y;
    const int i0 = blockIdx.x * 1024 + threadIdx.x;   // 4 strided float4s
    const float* s;
    __half* d;
    if (y < 4) {
        s = (y == 0) ? w0 : (y == 1) ? w1 : (y == 2) ? w2 : w3;
        d = wh4 + (size_t)y * NW;
    } else {
        const int q = y - 4;
        s = x + (size_t)q * NW;
        d = xh + (size_t)q * NW;
    }
#pragma unroll
    for (int j = 0; j < 4; ++j) cvt4(s, d, i0 + j * 256);
}

// ---------------------------------------------------------------------------
// GEMM: C = Ah(MxK) * Bh(NxK)^T, 1-term fp16.  (R14 config, unchanged)
// Tile 128x128x64, 8 warps (2m x 4n), XOR-swizzled smem, cp.async dbl-buf,
// 2 CTAs/SM, single barrier per chunk.
// ---------------------------------------------------------------------------
#define TILE  16384
#define GBUF  (2 * TILE)            // Ah, Bh
#define GEMM_SMEM (2 * GBUF)        // 65536

struct EpiQKV { __half* q; __half* k; __half* v; };

template <bool QKV>
__global__ void __launch_bounds__(256, 2)
gemm_h(const __half* __restrict__ Ah, const __half* __restrict__ Bh3,
       const float* __restrict__ bias, float* __restrict__ Cf, EpiQKV ep)
{
    extern __shared__ char smem[];
    const uint32_t sbase = smem_u32(smem);

    const int tid  = threadIdx.x;
    const int lane = tid & 31;
    const int warp = tid >> 5;
    const int wm   = warp >> 2;
    const int wn   = warp & 3;
    const int bm   = blockIdx.y * 128;

    int which = 0, bn = blockIdx.x * 128;
    const __half* Bh = Bh3;
    if (QKV) {
        which = blockIdx.x >> 3;
        bn    = (blockIdx.x & 7) * 128;
        Bh    = Bh3 + (size_t)which * NW;
    }

    const __half* Abase = Ah + (size_t)bm * EMB;
    const __half* Bbase = Bh + (size_t)bn * EMB;

    auto load_chunk = [&](int kc, uint32_t buf) {
        const int kofs = kc * 64;
#pragma unroll
        for (int i = 0; i < 4; ++i) {
            const int c    = i * 256 + tid;
            const int row  = c >> 3;
            const int c16  = c & 7;
            const uint32_t so = buf + (uint32_t)row * 128 +
                                (uint32_t)((c16 ^ (row & 7)) * 16);
            const size_t g = (size_t)row * EMB + kofs + c16 * 8;
            cp16(sbase + so,        Abase + g);
            cp16(sbase + so + TILE, Bbase + g);
        }
    };

    float acc[4][4][4];
#pragma unroll
    for (int i = 0; i < 4; ++i)
#pragma unroll
        for (int j = 0; j < 4; ++j)
#pragma unroll
            for (int k = 0; k < 4; ++k) acc[i][j][k] = 0.f;

    const int a_row = wm * 64 + (lane & 15);
    const int a_c16b = (lane >> 4);
    const int b_row = wn * 32 + ((lane >> 4) << 3) + (lane & 7);
    const int b_c16b = ((lane >> 3) & 1);

    load_chunk(0, 0);
    CP_COMMIT();

    for (int kc = 0; kc < 16; ++kc) {
        const uint32_t buf = (uint32_t)(kc & 1) * GBUF;
        CP_WAIT0();
        __syncthreads();
        if (kc < 15) {
            load_chunk(kc + 1, buf ^ GBUF);
            CP_COMMIT();
        }

#pragma unroll
        for (int ks = 0; ks < 4; ++ks) {
            uint32_t bf[4][2];
#pragma unroll
            for (int np = 0; np < 2; ++np) {
                const int row = b_row + np * 16;
                const int c16 = b_c16b + ks * 2;
                const uint32_t bo = sbase + buf + TILE + (uint32_t)row * 128 +
                                    (uint32_t)((c16 ^ (row & 7)) * 16);
                uint32_t t[4];
                ldsm_x4(t, bo);
                bf[2 * np][0] = t[0]; bf[2 * np][1] = t[1];
                bf[2 * np + 1][0] = t[2]; bf[2 * np + 1][1] = t[3];
            }
#pragma unroll
            for (int mt = 0; mt < 4; ++mt) {
                const int row = a_row + mt * 16;
                const int ac16 = ks * 2 + a_c16b;
                const uint32_t ao = sbase + buf + (uint32_t)row * 128 +
                                    (uint32_t)((ac16 ^ (row & 7)) * 16);
                uint32_t ah[4];
                ldsm_x4(ah, ao);
#pragma unroll
                for (int nt = 0; nt < 4; ++nt) mma16816(acc[mt][nt], ah, bf[nt]);
            }
        }
    }

    const int r0 = bm + wm * 64 + (lane >> 2);
    const int c0 = bn + wn * 32 + (lane & 3) * 2;
    __half* Ch = nullptr;
    float osc = 1.f;
    if (QKV) {
        Ch = (which == 0) ? ep.q : (which == 1) ? ep.k : ep.v;
        if (which == 0) osc = QSCALE;
    }
#pragma unroll
    for (int mt = 0; mt < 4; ++mt) {
#pragma unroll
        for (int nt = 0; nt < 4; ++nt) {
            const int row0 = r0 + mt * 16;
            const int row1 = row0 + 8;
            const int col  = c0 + nt * 8;
            if (!QKV) {
                const float b0 = bias[col], b1 = bias[col + 1];
                *(float2*)(Cf + (size_t)row0 * EMB + col) =
                    make_float2(acc[mt][nt][0] + b0, acc[mt][nt][1] + b1);
                *(float2*)(Cf + (size_t)row1 * EMB + col) =
                    make_float2(acc[mt][nt][2] + b0, acc[mt][nt][3] + b1);
            } else {
                const int h  = col >> 6;
                const int d  = col & 63;
                const int b0b = row0 >> 11, s0 = row0 & 2047;
                const int b1b = row1 >> 11, s1 = row1 & 2047;
                *(uint32_t*)(Ch + (((size_t)(b0b * NH + h) * SEQ + s0) * HD + d)) =
                    pack_h2(__float2half_rn(acc[mt][nt][0] * osc),
                            __float2half_rn(acc[mt][nt][1] * osc));
                *(uint32_t*)(Ch + (((size_t)(b1b * NH + h) * SEQ + s1) * HD + d)) =
                    pack_h2(__float2half_rn(acc[mt][nt][2] * osc),
                            __float2half_rn(acc[mt][nt][3] * osc));
            }
        }
    }
}

// ---------------------------------------------------------------------------
// Attention: FA2, fixed-offset softmax, 4 warps x 2 m-tiles (32 q-rows/warp),
// 128 threads, 64-key tiles, smem 36.9 KB (2 CTAs/SM).
// Row-sum l via deferred HADD2 trees on pa fragments (no ones-MMA):
// per-thread fp32 partials over its 16 columns, one 2-shuffle reduce at end.
// ---------------------------------------------------------------------------
#define AROWB 144
#define ATILE (64 * AROWB)           // 9216
#define ASMEM (4 * ATILE)            // 36864

__global__ void __launch_bounds__(128) attn_mma(__half* __restrict__ Oh)
{
    __shared__ __align__(128) char asmem[ASMEM];
    const uint32_t sb = smem_u32(asmem);

    const int tid  = threadIdx.x;
    const int lane = tid & 31;
    const int warp = tid >> 5;
    const int bh   = blockIdx.y;
    const int b    = bh >> 4;
    const int h    = bh & 15;
    const int q0   = blockIdx.x * 128;
    const size_t gbase = (size_t)bh * SEQ * HD;

    {
#pragma unroll
        for (int i = 0; i < 8; ++i) {
            const int c   = i * 128 + tid;
            const int row = c >> 3;
            const int c16 = c & 7;
            *(uint4*)(asmem + row * AROWB + c16 * 16) =
                *(const uint4*)(&g_Qh[gbase + (size_t)(q0 + row) * HD + c16 * 8]);
        }
    }
    __syncthreads();
    uint32_t qa[2][4][4];
#pragma unroll
    for (int mt = 0; mt < 2; ++mt) {
        const uint32_t aro = sb + (uint32_t)(warp * 32 + mt * 16 + (lane & 15)) * AROWB +
                             (uint32_t)((lane >> 4) * 8) * 2;
#pragma unroll
        for (int ks = 0; ks < 4; ++ks) ldsm_x4(qa[mt][ks], aro + ks * 32);
    }
    __syncthreads();

    const uint32_t b_ro = (uint32_t)(((lane >> 4) << 3) + (lane & 7)) * AROWB +
                          (uint32_t)(((lane >> 3) & 1) << 3) * 2;
    const uint32_t v_ro = (uint32_t)((((lane >> 3) & 1) << 3) + (lane & 7)) * AROWB +
                          (uint32_t)((lane >> 4) * 8) * 2;

    float oacc[2][8][4];
#pragma unroll
    for (int mt = 0; mt < 2; ++mt)
#pragma unroll
        for (int i = 0; i < 8; ++i)
#pragma unroll
            for (int k = 0; k < 4; ++k) oacc[mt][i][k] = 0.f;

    // per-thread fp32 row-sum partials: [mt][0]=rows r, [mt][1]=rows r+8
    float lr[2][2] = {{0.f, 0.f}, {0.f, 0.f}};

    auto load_kv = [&](int kt, uint32_t buf) {
        const __half* kg = &g_Kh[gbase + (size_t)kt * HD];
        const __half* vg = &g_Vh[gbase + (size_t)kt * HD];
#pragma unroll
        for (int i = 0; i < 4; ++i) {
            const int c   = i * 128 + tid;
            const int row = c >> 3;
            const int c16 = c & 7;
            const uint32_t so = buf + (uint32_t)row * AROWB + (uint32_t)c16 * 16;
            cp16(sb + so,          kg + (size_t)row * HD + c16 * 8);
            cp16(sb + so + ATILE,  vg + (size_t)row * HD + c16 * 8);
        }
    };

    load_kv(0, 0);
    CP_COMMIT();

    uint32_t pa[2][4][4];

    for (int ti = 0; ti < SEQ / 64; ++ti) {
        const uint32_t buf = (uint32_t)(ti & 1) * (2 * ATILE);
        CP_WAIT0();
        __syncthreads();
        if (ti < SEQ / 64 - 1) {
            load_kv((ti + 1) * 64, buf ^ (2 * ATILE));
            CP_COMMIT();
        }

        // ---- QK: accumulators start at -SOFF ----
        float sc[2][8][4];
#pragma unroll
        for (int mt = 0; mt < 2; ++mt)
#pragma unroll
            for (int i = 0; i < 8; ++i)
#pragma unroll
                for (int k = 0; k < 4; ++k) sc[mt][i][k] = -SOFF;

#pragma unroll
        for (int ks = 0; ks < 4; ++ks) {
            uint32_t bf[8][2];
#pragma unroll
            for (int np = 0; np < 4; ++np) {
                uint32_t t[4];
                ldsm_x4(t, sb + buf + b_ro + (uint32_t)np * 16 * AROWB + ks * 32);
                bf[2 * np][0] = t[0]; bf[2 * np][1] = t[1];
                bf[2 * np + 1][0] = t[2]; bf[2 * np + 1][1] = t[3];
            }
#pragma unroll
            for (int mt = 0; mt < 2; ++mt)
#pragma unroll
                for (int nt = 0; nt < 8; ++nt) mma16816(sc[mt][nt], qa[mt][ks], bf[nt]);
        }

        // ---- P = 2^sc, packed fp16x2 ----
#pragma unroll
        for (int mt = 0; mt < 2; ++mt)
#pragma unroll
            for (int nt = 0; nt < 8; ++nt) {
                pa[mt][nt >> 1][(nt & 1) * 2 + 0] = ex2_h2(sc[mt][nt][0], sc[mt][nt][1]);
                pa[mt][nt >> 1][(nt & 1) * 2 + 1] = ex2_h2(sc[mt][nt][2], sc[mt][nt][3]);
            }

        // ---- l partials via HADD2 trees (regs 0,2 = rows r; 1,3 = rows r+8) ----
#pragma unroll
        for (int mt = 0; mt < 2; ++mt) {
            uint32_t r0 = hadd2(hadd2(hadd2(pa[mt][0][0], pa[mt][1][0]),
                                      hadd2(pa[mt][2][0], pa[mt][3][0])),
                                hadd2(hadd2(pa[mt][0][2], pa[mt][1][2]),
                                      hadd2(pa[mt][2][2], pa[mt][3][2])));
            uint32_t r1 = hadd2(hadd2(hadd2(pa[mt][0][1], pa[mt][1][1]),
                                      hadd2(pa[mt][2][1], pa[mt][3][1])),
                                hadd2(hadd2(pa[mt][0][3], pa[mt][1][3]),
                                      hadd2(pa[mt][2][3], pa[mt][3][3])));
            float2 f0 = __half22float2(*(__half2*)&r0);
            float2 f1 = __half22float2(*(__half2*)&r1);
            lr[mt][0] += f0.x + f0.y;
            lr[mt][1] += f1.x + f1.y;
        }

        // ---- PV ----
#pragma unroll
        for (int ks = 0; ks < 4; ++ks) {
            uint32_t vf[8][2];
#pragma unroll
            for (int dp = 0; dp < 4; ++dp) {
                uint32_t t[4];
                ldsm_x4_t(t, sb + buf + ATILE + v_ro +
                             (uint32_t)ks * 16 * AROWB + dp * 32);
                vf[2 * dp][0] = t[0]; vf[2 * dp][1] = t[1];
                vf[2 * dp + 1][0] = t[2]; vf[2 * dp + 1][1] = t[3];
            }
#pragma unroll
            for (int mt = 0; mt < 2; ++mt)
#pragma unroll
                for (int nt = 0; nt < 8; ++nt) mma16816(oacc[mt][nt], pa[mt][ks], vf[nt]);
        }
    }

    // ---- finalize row sums across the 4-lane quad ----
#pragma unroll
    for (int mt = 0; mt < 2; ++mt)
#pragma unroll
        for (int j = 0; j < 2; ++j) {
            lr[mt][j] += __shfl_xor_sync(0xFFFFFFFFu, lr[mt][j], 1);
            lr[mt][j] += __shfl_xor_sync(0xFFFFFFFFu, lr[mt][j], 2);
        }

    // ---- epilogue: fp16 hi at [b,s,h,d] ----
#pragma unroll
    for (int mt = 0; mt < 2; ++mt) {
        const float i0 = 1.0f / lr[mt][0];
        const float i1 = 1.0f / lr[mt][1];
        const int row0 = q0 + warp * 32 + mt * 16 + (lane >> 2);
        const int row1 = row0 + 8;
        const size_t off0 = ((size_t)b * SEQ + row0) * EMB + h * HD;
        const size_t off1 = ((size_t)b * SEQ + row1) * EMB + h * HD;
#pragma unroll
        for (int nt = 0; nt < 8; ++nt) {
            const int d = nt * 8 + (lane & 3) * 2;
            *(uint32_t*)(Oh + off0 + d) =
                pack_h2(__float2half_rn(oacc[mt][nt][0] * i0),
                        __float2half_rn(oacc[mt][nt][1] * i0));
            *(uint32_t*)(Oh + off1 + d) =
                pack_h2(__float2half_rn(oacc[mt][nt][2] * i1),
                        __float2half_rn(oacc[mt][nt][3] * i1));
        }
    }
}

// ---------------------------------------------------------------------------
extern "C" void kernel_launch(void* const* d_in, const int* in_sizes, int n_in,
                              void* d_out, int out_size)
{
    const float* x  = (const float*)d_in[0];
    const float* Wq = (const float*)d_in[1];
    const float* Wk = (const float*)d_in[2];
    const float* Wv = (const float*)d_in[3];
    const float* Wo = (const float*)d_in[4];
    const float* bo = (const float*)d_in[5];
    float* out = (float*)d_out;

    cudaFuncSetAttribute(gemm_h<true>,
                         cudaFuncAttributeMaxDynamicSharedMemorySize, GEMM_SMEM);
    cudaFuncSetAttribute(gemm_h<false>,
                         cudaFuncAttributeMaxDynamicSharedMemorySize, GEMM_SMEM);

    __half *xh, *wh, *qh, *kh, *vh;
    cudaGetSymbolAddress((void**)&xh, g_xh);
    cudaGetSymbolAddress((void**)&wh, g_Wh4);
    cudaGetSymbolAddress((void**)&qh, g_Qh);
    cudaGetSymbolAddress((void**)&kh, g_Kh);
    cudaGetSymbolAddress((void**)&vh, g_Vh);

    const int nW4 = NW / 4;   // 262144

    EpiQKV ep{qh, kh, vh};
    EpiQKV ep0{nullptr, nullptr, nullptr};

    // one merged convert (4 float4/thread): W -> slots 0..3; x -> xh
    cvt_all<<<dim3(nW4 / 1024, 8), 256>>>(x, Wq, Wk, Wv, Wo, wh, xh);

    // fused Q/K/V projection, 1-term: grid (24, 32)
    gemm_h<true><<<dim3(24, MROWS / 128), 256, GEMM_SMEM>>>(
        xh, wh, nullptr, nullptr, ep);

    // attention: 128 q rows/CTA, 128 threads, 64-key tiles
    attn_mma<<<dim3(SEQ / 128, BH), 128>>>(xh);

    // output projection, 1-term; Wo = slot 3
    gemm_h<false><<<dim3(8, MROWS / 128), 256, GEMM_SMEM>>>(
        xh, wh + (size_t)3 * NW, bo, out, ep0);
}

// round 16
// speedup vs baseline: 1.0162x; 1.0162x over previous
#include <cuda_runtime.h>
#include <cuda_fp16.h>
#include <cstdint>

// Problem constants
#define BATCH 2
#define SEQ   2048
#define EMB   1024
#define NH    16
#define HD    64
#define MROWS (BATCH * SEQ)      // 4096
#define BH    (BATCH * NH)       // 32
#define NW    (EMB * EMB)        // 1048576

// Scratch (device globals)
__device__ __half g_xh[MROWS * EMB];    // activation hi (x, later attn-out)
__device__ __half g_Wh4[4 * NW];        // weight hi x4 (Wq,Wk,Wv,Wo)
__device__ __half g_Qh[BH * SEQ * HD];  // [b,h,s,d] fp16 (pre-scaled by 0.125*log2e)
__device__ __half g_Kh[BH * SEQ * HD];
__device__ __half g_Vh[BH * SEQ * HD];

// ---------------------------------------------------------------------------
// helpers
// ---------------------------------------------------------------------------
__device__ __forceinline__ uint32_t smem_u32(const void* p) {
    uint32_t a;
    asm("{ .reg .u64 t; cvta.to.shared.u64 t, %1; cvt.u32.u64 %0, t; }"
        : "=r"(a) : "l"(p));
    return a;
}
__device__ __forceinline__ void ldsm_x4(uint32_t* r, uint32_t addr) {
    asm volatile("ldmatrix.sync.aligned.m8n8.x4.shared.b16 {%0,%1,%2,%3}, [%4];"
                 : "=r"(r[0]), "=r"(r[1]), "=r"(r[2]), "=r"(r[3]) : "r"(addr));
}
__device__ __forceinline__ void ldsm_x4_t(uint32_t* r, uint32_t addr) {
    asm volatile("ldmatrix.sync.aligned.m8n8.x4.trans.shared.b16 {%0,%1,%2,%3}, [%4];"
                 : "=r"(r[0]), "=r"(r[1]), "=r"(r[2]), "=r"(r[3]) : "r"(addr));
}
__device__ __forceinline__ void mma16816(float* c, const uint32_t* a, const uint32_t* b) {
    asm volatile("mma.sync.aligned.m16n8k16.row.col.f32.f16.f16.f32 "
                 "{%0,%1,%2,%3}, {%4,%5,%6,%7}, {%8,%9}, {%0,%1,%2,%3};"
                 : "+f"(c[0]), "+f"(c[1]), "+f"(c[2]), "+f"(c[3])
                 : "r"(a[0]), "r"(a[1]), "r"(a[2]), "r"(a[3]),
                   "r"(b[0]), "r"(b[1]));
}
__device__ __forceinline__ uint32_t pack_h2(__half a, __half b) {
    __half2 h = __halves2half2(a, b);
    return *reinterpret_cast<uint32_t*>(&h);
}
__device__ __forceinline__ uint32_t ex2_h2(float lo, float hi) {
    uint32_t h, r;
    asm("cvt.rn.f16x2.f32 %0, %1, %2;" : "=r"(h) : "f"(hi), "f"(lo));
    asm("ex2.approx.f16x2 %0, %1;" : "=r"(r) : "r"(h));
    return r;
}
__device__ __forceinline__ uint32_t hadd2(uint32_t a, uint32_t b) {
    uint32_t r;
    asm("add.f16x2 %0, %1, %2;" : "=r"(r) : "r"(a), "r"(b));
    return r;
}
__device__ __forceinline__ void cp16(uint32_t saddr, const void* g) {
    asm volatile("cp.async.cg.shared.global [%0], [%1], 16;"
                 :: "r"(saddr), "l"(g) : "memory");
}
#define CP_COMMIT() asm volatile("cp.async.commit_group;" ::: "memory")
#define CP_WAIT0()  asm volatile("cp.async.wait_group 0;" ::: "memory")

#define QSCALE 0.18033688f   // 0.125 * log2(e)
#define SOFF   8.0f          // fixed softmax offset (log2 units); cancels in p/l

// ---------------------------------------------------------------------------
// merged fp32->fp16 convert, 4 float4 per thread (MLP=4):
// y=0..3 -> W slots, y=4..7 -> quarters of x
// ---------------------------------------------------------------------------
__device__ __forceinline__ void cvt4(const float* __restrict__ src,
                                     __half* __restrict__ hi, int i) {
    float4 v = ((const float4*)src)[i];
    ((uint2*)hi)[i] = make_uint2(
        pack_h2(__float2half_rn(v.x), __float2half_rn(v.y)),
        pack_h2(__float2half_rn(v.z), __float2half_rn(v.w)));
}

__global__ void __launch_bounds__(256)
cvt_all(const float* __restrict__ x,
        const float* __restrict__ w0, const float* __restrict__ w1,
        const float* __restrict__ w2, const float* __restrict__ w3,
        __half* __restrict__ wh4, __half* __restrict__ xh)
{
    const int y  = blockIdx.y;
    const int i0 = blockIdx.x * 1024 + threadIdx.x;   // 4 strided float4s
    const float* s;
    __half* d;
    if (y < 4) {
        s = (y == 0) ? w0 : (y == 1) ? w1 : (y == 2) ? w2 : w3;
        d = wh4 + (size_t)y * NW;
    } else {
        const int q = y - 4;
        s = x + (size_t)q * NW;
        d = xh + (size_t)q * NW;
    }
#pragma unroll
    for (int j = 0; j < 4; ++j) cvt4(s, d, i0 + j * 256);
}

// ---------------------------------------------------------------------------
// GEMM: C = Ah(MxK) * Bh(NxK)^T, 1-term fp16.
// Tile 128x128x64, 4 warps (2m x 2n, warp tile 64x64 -> 4 MMA per LDSM,
// matching attention's measured-best ratio), XOR-swizzled smem,
// cp.async dbl-buffered, 2 CTAs/SM (8 warps/SM = 2/SMSP).
// ---------------------------------------------------------------------------
#define TILE  16384
#define GBUF  (2 * TILE)            // Ah, Bh
#define GEMM_SMEM (2 * GBUF)        // 65536

struct EpiQKV { __half* q; __half* k; __half* v; };

template <bool QKV>
__global__ void __launch_bounds__(128, 2)
gemm_h(const __half* __restrict__ Ah, const __half* __restrict__ Bh3,
       const float* __restrict__ bias, float* __restrict__ Cf, EpiQKV ep)
{
    extern __shared__ char smem[];
    const uint32_t sbase = smem_u32(smem);

    const int tid  = threadIdx.x;      // 0..127
    const int lane = tid & 31;
    const int warp = tid >> 5;         // 0..3
    const int wm   = warp >> 1;        // 0..1
    const int wn   = warp & 1;         // 0..1
    const int bm   = blockIdx.y * 128;

    int which = 0, bn = blockIdx.x * 128;
    const __half* Bh = Bh3;
    if (QKV) {
        which = blockIdx.x >> 3;
        bn    = (blockIdx.x & 7) * 128;
        Bh    = Bh3 + (size_t)which * NW;
    }

    const __half* Abase = Ah + (size_t)bm * EMB;
    const __half* Bbase = Bh + (size_t)bn * EMB;

    // loader: 2048 chunk16 per double-tile, 128 threads x 16
    auto load_chunk = [&](int kc, uint32_t buf) {
        const int kofs = kc * 64;
#pragma unroll
        for (int i = 0; i < 8; ++i) {
            const int c    = i * 128 + tid;       // 0..1023
            const int row  = c >> 3;
            const int c16  = c & 7;
            const uint32_t so = buf + (uint32_t)row * 128 +
                                (uint32_t)((c16 ^ (row & 7)) * 16);
            const size_t g = (size_t)row * EMB + kofs + c16 * 8;
            cp16(sbase + so,        Abase + g);
            cp16(sbase + so + TILE, Bbase + g);
        }
    };

    float acc[4][8][4];
#pragma unroll
    for (int i = 0; i < 4; ++i)
#pragma unroll
        for (int j = 0; j < 8; ++j)
#pragma unroll
            for (int k = 0; k < 4; ++k) acc[i][j][k] = 0.f;

    const int a_row  = wm * 64 + (lane & 15);                     // + mt*16
    const int a_c16b = (lane >> 4);                               // + ks*2
    const int b_row  = wn * 64 + ((lane >> 4) << 3) + (lane & 7); // + np*16
    const int b_c16b = ((lane >> 3) & 1);                         // + ks*2

    load_chunk(0, 0);
    CP_COMMIT();

    for (int kc = 0; kc < 16; ++kc) {
        const uint32_t buf = (uint32_t)(kc & 1) * GBUF;
        CP_WAIT0();
        __syncthreads();
        if (kc < 15) {
            load_chunk(kc + 1, buf ^ GBUF);
            CP_COMMIT();
        }

#pragma unroll
        for (int ks = 0; ks < 4; ++ks) {
            uint32_t bf[8][2];
#pragma unroll
            for (int np = 0; np < 4; ++np) {
                const int row = b_row + np * 16;
                const int c16 = b_c16b + ks * 2;
                const uint32_t bo = sbase + buf + TILE + (uint32_t)row * 128 +
                                    (uint32_t)((c16 ^ (row & 7)) * 16);
                uint32_t t[4];
                ldsm_x4(t, bo);
                bf[2 * np][0] = t[0]; bf[2 * np][1] = t[1];
                bf[2 * np + 1][0] = t[2]; bf[2 * np + 1][1] = t[3];
            }
#pragma unroll
            for (int mt = 0; mt < 4; ++mt) {
                const int row  = a_row + mt * 16;
                const int ac16 = ks * 2 + a_c16b;
                const uint32_t ao = sbase + buf + (uint32_t)row * 128 +
                                    (uint32_t)((ac16 ^ (row & 7)) * 16);
                uint32_t ah[4];
                ldsm_x4(ah, ao);
#pragma unroll
                for (int nt = 0; nt < 8; ++nt) mma16816(acc[mt][nt], ah, bf[nt]);
            }
        }
    }

    const int r0 = bm + wm * 64 + (lane >> 2);
    const int c0 = bn + wn * 64 + (lane & 3) * 2;
    __half* Ch = nullptr;
    float osc = 1.f;
    if (QKV) {
        Ch = (which == 0) ? ep.q : (which == 1) ? ep.k : ep.v;
        if (which == 0) osc = QSCALE;
    }
#pragma unroll
    for (int mt = 0; mt < 4; ++mt) {
#pragma unroll
        for (int nt = 0; nt < 8; ++nt) {
            const int row0 = r0 + mt * 16;
            const int row1 = row0 + 8;
            const int col  = c0 + nt * 8;
            if (!QKV) {
                const float b0 = bias[col], b1 = bias[col + 1];
                *(float2*)(Cf + (size_t)row0 * EMB + col) =
                    make_float2(acc[mt][nt][0] + b0, acc[mt][nt][1] + b1);
                *(float2*)(Cf + (size_t)row1 * EMB + col) =
                    make_float2(acc[mt][nt][2] + b0, acc[mt][nt][3] + b1);
            } else {
                const int h  = col >> 6;
                const int d  = col & 63;
                const int b0b = row0 >> 11, s0 = row0 & 2047;
                const int b1b = row1 >> 11, s1 = row1 & 2047;
                *(uint32_t*)(Ch + (((size_t)(b0b * NH + h) * SEQ + s0) * HD + d)) =
                    pack_h2(__float2half_rn(acc[mt][nt][0] * osc),
                            __float2half_rn(acc[mt][nt][1] * osc));
                *(uint32_t*)(Ch + (((size_t)(b1b * NH + h) * SEQ + s1) * HD + d)) =
                    pack_h2(__float2half_rn(acc[mt][nt][2] * osc),
                            __float2half_rn(acc[mt][nt][3] * osc));
            }
        }
    }
}

// ---------------------------------------------------------------------------
// Attention (R15 config — measured-best): FA2, fixed-offset softmax,
// 4 warps x 2 m-tiles (32 q-rows/warp), 128 threads, 64-key tiles,
// smem 36.9 KB (2 CTAs/SM). Row-sum via HADD2 trees; output fp16 hi.
// ---------------------------------------------------------------------------
#define AROWB 144
#define ATILE (64 * AROWB)           // 9216
#define ASMEM (4 * ATILE)            // 36864

__global__ void __launch_bounds__(128) attn_mma(__half* __restrict__ Oh)
{
    __shared__ __align__(128) char asmem[ASMEM];
    const uint32_t sb = smem_u32(asmem);

    const int tid  = threadIdx.x;
    const int lane = tid & 31;
    const int warp = tid >> 5;
    const int bh   = blockIdx.y;
    const int b    = bh >> 4;
    const int h    = bh & 15;
    const int q0   = blockIdx.x * 128;
    const size_t gbase = (size_t)bh * SEQ * HD;

    {
#pragma unroll
        for (int i = 0; i < 8; ++i) {
            const int c   = i * 128 + tid;
            const int row = c >> 3;
            const int c16 = c & 7;
            *(uint4*)(asmem + row * AROWB + c16 * 16) =
                *(const uint4*)(&g_Qh[gbase + (size_t)(q0 + row) * HD + c16 * 8]);
        }
    }
    __syncthreads();
    uint32_t qa[2][4][4];
#pragma unroll
    for (int mt = 0; mt < 2; ++mt) {
        const uint32_t aro = sb + (uint32_t)(warp * 32 + mt * 16 + (lane & 15)) * AROWB +
                             (uint32_t)((lane >> 4) * 8) * 2;
#pragma unroll
        for (int ks = 0; ks < 4; ++ks) ldsm_x4(qa[mt][ks], aro + ks * 32);
    }
    __syncthreads();

    const uint32_t b_ro = (uint32_t)(((lane >> 4) << 3) + (lane & 7)) * AROWB +
                          (uint32_t)(((lane >> 3) & 1) << 3) * 2;
    const uint32_t v_ro = (uint32_t)((((lane >> 3) & 1) << 3) + (lane & 7)) * AROWB +
                          (uint32_t)((lane >> 4) * 8) * 2;

    float oacc[2][8][4];
#pragma unroll
    for (int mt = 0; mt < 2; ++mt)
#pragma unroll
        for (int i = 0; i < 8; ++i)
#pragma unroll
            for (int k = 0; k < 4; ++k) oacc[mt][i][k] = 0.f;

    float lr[2][2] = {{0.f, 0.f}, {0.f, 0.f}};

    auto load_kv = [&](int kt, uint32_t buf) {
        const __half* kg = &g_Kh[gbase + (size_t)kt * HD];
        const __half* vg = &g_Vh[gbase + (size_t)kt * HD];
#pragma unroll
        for (int i = 0; i < 4; ++i) {
            const int c   = i * 128 + tid;
            const int row = c >> 3;
            const int c16 = c & 7;
            const uint32_t so = buf + (uint32_t)row * AROWB + (uint32_t)c16 * 16;
            cp16(sb + so,          kg + (size_t)row * HD + c16 * 8);
            cp16(sb + so + ATILE,  vg + (size_t)row * HD + c16 * 8);
        }
    };

    load_kv(0, 0);
    CP_COMMIT();

    uint32_t pa[2][4][4];

    for (int ti = 0; ti < SEQ / 64; ++ti) {
        const uint32_t buf = (uint32_t)(ti & 1) * (2 * ATILE);
        CP_WAIT0();
        __syncthreads();
        if (ti < SEQ / 64 - 1) {
            load_kv((ti + 1) * 64, buf ^ (2 * ATILE));
            CP_COMMIT();
        }

        // ---- QK: accumulators start at -SOFF ----
        float sc[2][8][4];
#pragma unroll
        for (int mt = 0; mt < 2; ++mt)
#pragma unroll
            for (int i = 0; i < 8; ++i)
#pragma unroll
                for (int k = 0; k < 4; ++k) sc[mt][i][k] = -SOFF;

#pragma unroll
        for (int ks = 0; ks < 4; ++ks) {
            uint32_t bf[8][2];
#pragma unroll
            for (int np = 0; np < 4; ++np) {
                uint32_t t[4];
                ldsm_x4(t, sb + buf + b_ro + (uint32_t)np * 16 * AROWB + ks * 32);
                bf[2 * np][0] = t[0]; bf[2 * np][1] = t[1];
                bf[2 * np + 1][0] = t[2]; bf[2 * np + 1][1] = t[3];
            }
#pragma unroll
            for (int mt = 0; mt < 2; ++mt)
#pragma unroll
                for (int nt = 0; nt < 8; ++nt) mma16816(sc[mt][nt], qa[mt][ks], bf[nt]);
        }

        // ---- P = 2^sc, packed fp16x2 ----
#pragma unroll
        for (int mt = 0; mt < 2; ++mt)
#pragma unroll
            for (int nt = 0; nt < 8; ++nt) {
                pa[mt][nt >> 1][(nt & 1) * 2 + 0] = ex2_h2(sc[mt][nt][0], sc[mt][nt][1]);
                pa[mt][nt >> 1][(nt & 1) * 2 + 1] = ex2_h2(sc[mt][nt][2], sc[mt][nt][3]);
            }

        // ---- l partials via HADD2 trees ----
#pragma unroll
        for (int mt = 0; mt < 2; ++mt) {
            uint32_t r0 = hadd2(hadd2(hadd2(pa[mt][0][0], pa[mt][1][0]),
                                      hadd2(pa[mt][2][0], pa[mt][3][0])),
                                hadd2(hadd2(pa[mt][0][2], pa[mt][1][2]),
                                      hadd2(pa[mt][2][2], pa[mt][3][2])));
            uint32_t r1 = hadd2(hadd2(hadd2(pa[mt][0][1], pa[mt][1][1]),
                                      hadd2(pa[mt][2][1], pa[mt][3][1])),
                                hadd2(hadd2(pa[mt][0][3], pa[mt][1][3]),
                                      hadd2(pa[mt][2][3], pa[mt][3][3])));
            float2 f0 = __half22float2(*(__half2*)&r0);
            float2 f1 = __half22float2(*(__half2*)&r1);
            lr[mt][0] += f0.x + f0.y;
            lr[mt][1] += f1.x + f1.y;
        }

        // ---- PV ----
#pragma unroll
        for (int ks = 0; ks < 4; ++ks) {
            uint32_t vf[8][2];
#pragma unroll
            for (int dp = 0; dp < 4; ++dp) {
                uint32_t t[4];
                ldsm_x4_t(t, sb + buf + ATILE + v_ro +
                             (uint32_t)ks * 16 * AROWB + dp * 32);
                vf[2 * dp][0] = t[0]; vf[2 * dp][1] = t[1];
                vf[2 * dp + 1][0] = t[2]; vf[2 * dp + 1][1] = t[3];
            }
#pragma unroll
            for (int mt = 0; mt < 2; ++mt)
#pragma unroll
                for (int nt = 0; nt < 8; ++nt) mma16816(oacc[mt][nt], pa[mt][ks], vf[nt]);
        }
    }

    // ---- finalize row sums across the 4-lane quad ----
#pragma unroll
    for (int mt = 0; mt < 2; ++mt)
#pragma unroll
        for (int j = 0; j < 2; ++j) {
            lr[mt][j] += __shfl_xor_sync(0xFFFFFFFFu, lr[mt][j], 1);
            lr[mt][j] += __shfl_xor_sync(0xFFFFFFFFu, lr[mt][j], 2);
        }

    // ---- epilogue: fp16 hi at [b,s,h,d] ----
#pragma unroll
    for (int mt = 0; mt < 2; ++mt) {
        const float i0 = 1.0f / lr[mt][0];
        const float i1 = 1.0f / lr[mt][1];
        const int row0 = q0 + warp * 32 + mt * 16 + (lane >> 2);
        const int row1 = row0 + 8;
        const size_t off0 = ((size_t)b * SEQ + row0) * EMB + h * HD;
        const size_t off1 = ((size_t)b * SEQ + row1) * EMB + h * HD;
#pragma unroll
        for (int nt = 0; nt < 8; ++nt) {
            const int d = nt * 8 + (lane & 3) * 2;
            *(uint32_t*)(Oh + off0 + d) =
                pack_h2(__float2half_rn(oacc[mt][nt][0] * i0),
                        __float2half_rn(oacc[mt][nt][1] * i0));
            *(uint32_t*)(Oh + off1 + d) =
                pack_h2(__float2half_rn(oacc[mt][nt][2] * i1),
                        __float2half_rn(oacc[mt][nt][3] * i1));
        }
    }
}

// ---------------------------------------------------------------------------
extern "C" void kernel_launch(void* const* d_in, const int* in_sizes, int n_in,
                              void* d_out, int out_size)
{
    const float* x  = (const float*)d_in[0];
    const float* Wq = (const float*)d_in[1];
    const float* Wk = (const float*)d_in[2];
    const float* Wv = (const float*)d_in[3];
    const float* Wo = (const float*)d_in[4];
    const float* bo = (const float*)d_in[5];
    float* out = (float*)d_out;

    cudaFuncSetAttribute(gemm_h<true>,
                         cudaFuncAttributeMaxDynamicSharedMemorySize, GEMM_SMEM);
    cudaFuncSetAttribute(gemm_h<false>,
                         cudaFuncAttributeMaxDynamicSharedMemorySize, GEMM_SMEM);

    __half *xh, *wh, *qh, *kh, *vh;
    cudaGetSymbolAddress((void**)&xh, g_xh);
    cudaGetSymbolAddress((void**)&wh, g_Wh4);
    cudaGetSymbolAddress((void**)&qh, g_Qh);
    cudaGetSymbolAddress((void**)&kh, g_Kh);
    cudaGetSymbolAddress((void**)&vh, g_Vh);

    const int nW4 = NW / 4;   // 262144

    EpiQKV ep{qh, kh, vh};
    EpiQKV ep0{nullptr, nullptr, nullptr};

    // one merged convert (4 float4/thread): W -> slots 0..3; x -> xh
    cvt_all<<<dim3(nW4 / 1024, 8), 256>>>(x, Wq, Wk, Wv, Wo, wh, xh);

    // fused Q/K/V projection, 1-term: grid (24, 32), 128 threads
    gemm_h<true><<<dim3(24, MROWS / 128), 128, GEMM_SMEM>>>(
        xh, wh, nullptr, nullptr, ep);

    // attention: 128 q rows/CTA, 128 threads, 64-key tiles
    attn_mma<<<dim3(SEQ / 128, BH), 128>>>(xh);

    // output projection, 1-term; Wo = slot 3
    gemm_h<false><<<dim3(8, MROWS / 128), 128, GEMM_SMEM>>>(
        xh, wh + (size_t)3 * NW, bo, out, ep0);
}